// round 15
// baseline (speedup 1.0000x reference)
#include <cuda_runtime.h>
#include <cstdint>

#define HEADS 32
#define S_LEN 2048
#define DIM   128
#define LOCAL 16

#define KBUF (64*64)            // 4096 words (K row = 64 words, XOR-swizzled)
#define VBUF (128*32)           // 4096 words (V dim-row = 32 words, XOR-swizzled)
#define SMEM_WORDS (2*KBUF + 2*VBUF)   // 16384 words = 65536 B
#define NJOBS 1024
#define GRID_PERSIST 444

__device__ unsigned g_Kp16[(size_t)HEADS * S_LEN * 64];
__device__ unsigned g_V16 [(size_t)HEADS * 32 * 128 * 32];
__device__ unsigned g_jobCtr;

__device__ __forceinline__ unsigned pack_f16x2(float lo_el, float hi_el) {
    unsigned r; asm("cvt.rn.f16x2.f32 %0, %1, %2;" : "=r"(r) : "f"(hi_el), "f"(lo_el)); return r;
}
__device__ __forceinline__ float fexp2(float x) {
    float y; asm("ex2.approx.ftz.f32 %0, %1;" : "=f"(y) : "f"(x)); return y;
}
__device__ __forceinline__ void mma_f16(float c[4],
                                        unsigned a0, unsigned a1, unsigned a2, unsigned a3,
                                        unsigned b0, unsigned b1) {
    asm volatile(
        "mma.sync.aligned.m16n8k16.row.col.f32.f16.f16.f32 "
        "{%0,%1,%2,%3}, {%4,%5,%6,%7}, {%8,%9}, {%0,%1,%2,%3};"
        : "+f"(c[0]), "+f"(c[1]), "+f"(c[2]), "+f"(c[3])
        : "r"(a0), "r"(a1), "r"(a2), "r"(a3), "r"(b0), "r"(b1));
}
__device__ __forceinline__ uint32_t smem_u32(const void* p) {
    uint32_t a;
    asm("{ .reg .u64 t; cvta.to.shared.u64 t, %1; cvt.u32.u64 %0, t; }" : "=r"(a) : "l"(p));
    return a;
}
__device__ __forceinline__ void cp16(uint32_t dst, const void* src) {
    asm volatile("cp.async.ca.shared.global [%0], [%1], 16;" :: "r"(dst), "l"(src));
}
#define CP_COMMIT() asm volatile("cp.async.commit_group;" ::: "memory")
#define CP_WAIT0()  asm volatile("cp.async.wait_group 0;" ::: "memory")

// ---- merged prepass: K fp16x2 mma-ready + V fp16x2 dim-major permuted + counter reset ----
// K part: 4096 blocks; V part: 2048 blocks (32B-contiguous writes per thread)
__global__ __launch_bounds__(256)
void prepack_all_kernel(const float* __restrict__ K, const float* __restrict__ V) {
    if (blockIdx.x == 0 && threadIdx.x == 0) g_jobCtr = 0u;
    if (blockIdx.x < 4096) {
        const int gid = blockIdx.x * 256 + threadIdx.x;
        const int rid = gid >> 4;
        const int j   = gid & 15;
        const int h   = rid >> 11;
        const int s   = rid & 2047;
        const size_t src_row = ((size_t)s * HEADS + h) * DIM;
        unsigned kw[4];
        #pragma unroll
        for (int m = 0; m < 4; ++m) {
            const int i  = 4 * j + m;
            const int p  = i >> 4;
            const int lc = (i >> 2) & 3;
            const int s2 = i & 3;
            const int kg = 2 * p + (s2 >> 1);
            const int d  = kg * 16 + lc * 4 + (s2 & 1) * 2;
            const float2 v = __ldg((const float2*)(K + src_row + d));
            kw[m] = pack_f16x2(v.x, v.y);
        }
        *(uint4*)&g_Kp16[(size_t)rid * 64 + j * 4] = make_uint4(kw[0], kw[1], kw[2], kw[3]);
    } else {
        // V: thread covers (rid, d, jj) -> 8 words (32B) contiguous
        const int gid = (blockIdx.x - 4096) * 256 + threadIdx.x;   // 512K jobs
        const int rid = gid >> 9;        // h*32 + kb
        const int t2  = gid & 511;
        const int d   = t2 & 127;
        const int jj  = t2 >> 7;         // 0..3
        const int h   = rid >> 5;
        const int kb  = rid & 31;
        unsigned vw[8];
        #pragma unroll
        for (int m = 0; m < 8; ++m) {
            const int wp = 8 * jj + m;               // stored position
            const int w  = (wp >> 3) + (wp & 7) * 4; // logical token pair
            const int tok = kb * 64 + 2 * w;
            const float a = __ldg(V + ((size_t)tok       * HEADS + h) * DIM + d);
            const float b = __ldg(V + ((size_t)(tok + 1) * HEADS + h) * DIM + d);
            vw[m] = pack_f16x2(a, b);
        }
        unsigned* dst = &g_V16[((size_t)rid * 128 + d) * 32 + 8 * jj];
        *(uint4*)(dst)     = make_uint4(vw[0], vw[1], vw[2], vw[3]);
        *(uint4*)(dst + 4) = make_uint4(vw[4], vw[5], vw[6], vw[7]);
    }
}

__global__ __launch_bounds__(128, 3)
void sparse_attn_fu_kernel(const float* __restrict__ Q,
                           float* __restrict__ O) {
    extern __shared__ unsigned sm[];
    __shared__ unsigned jobSh;
    const uint32_t sbBase = smem_u32(sm);

    const int t    = threadIdx.x;   // 0..127
    const int w    = t >> 5;
    const int lane = t & 31;
    const int lr   = lane >> 2;
    const int lc   = lane & 3;
    const int kx   = (lr & 1) << 2;   // K swizzle term
    const int vx   = lr & 1;          // V swizzle term
    const float scale2 = 0.12751743f; // log2(e)/sqrt(128)

    // ---- first job (prefetch pattern: jobSh always holds the NEXT job) ----
    if (t == 0) jobSh = atomicAdd(&g_jobCtr, 1u);
    __syncthreads();
    unsigned j = jobSh;

    for (;;) {
        if (j >= NJOBS) break;
        if (t == 0) jobSh = atomicAdd(&g_jobCtr, 1u);   // prefetch next job id

        const int qb = 31 - (int)(j >> 5);    // heavy-first (LPT)
        const int h  = (int)(j & 31u);

        const int s0 = qb * 64 + w * 16 + lr;
        const int s1 = s0 + 8;
        const size_t hK = (size_t)h * S_LEN * 64;

        // ---- Q fragments (scale*log2e folded) ----
        unsigned qa[8][4];
        {
            const float* Qp0 = Q + ((size_t)s0 * HEADS + h) * DIM;
            const float* Qp1 = Q + ((size_t)s1 * HEADS + h) * DIM;
            #pragma unroll
            for (int kg = 0; kg < 8; ++kg) {
                const float4 A = *(const float4*)(Qp0 + kg * 16 + lc * 4);
                const float4 B = *(const float4*)(Qp1 + kg * 16 + lc * 4);
                qa[kg][0] = pack_f16x2(A.x * scale2, A.y * scale2);
                qa[kg][1] = pack_f16x2(B.x * scale2, B.y * scale2);
                qa[kg][2] = pack_f16x2(A.z * scale2, A.w * scale2);
                qa[kg][3] = pack_f16x2(B.z * scale2, B.w * scale2);
            }
        }

        float oacc[16][4];
        #pragma unroll
        for (int nt = 0; nt < 16; ++nt)
            #pragma unroll
            for (int q4 = 0; q4 < 4; ++q4) oacc[nt][q4] = 0.0f;
        float ls0 = 0.0f, ls1 = 0.0f;

        // ---- first allowed kv block; prologue K+V into buffer 0 ----
        int kb = 0;
        while (!(((qb - kb) < LOCAL) || (((kb + h + 1) & 7) == 0))) ++kb;
        {
            const unsigned* gK = g_Kp16 + hK + (size_t)kb * 64 * 64;
            const unsigned* gV = g_V16 + ((size_t)(h * 32 + kb) * 128) * 32;
            #pragma unroll
            for (int it = 0; it < 8; ++it) {
                const int c = t + it * 128;
                const int r = c >> 4, w4 = c & 15;
                cp16(sbBase + (r * 64 + (w4 ^ ((r & 1) << 2)) * 4) * 4, gK + r * 64 + w4 * 4);
            }
            #pragma unroll
            for (int it = 0; it < 8; ++it) {
                const int c = t + it * 128;
                const int r = c >> 3, w4 = c & 7;
                cp16(sbBase + (2 * KBUF + r * 32 + (w4 ^ (r & 1)) * 4) * 4, gV + r * 32 + w4 * 4);
            }
            CP_COMMIT();
        }

        int cur = 0;
        while (kb >= 0) {
            int kbn = kb + 1;
            while (kbn <= qb && !(((qb - kbn) < LOCAL) || (((kbn + h + 1) & 7) == 0))) ++kbn;
            if (kbn > qb) kbn = -1;

            CP_WAIT0();          // K(kb)+V(kb) resident (issued a full phase ago)
            __syncthreads();     // visible to all; other buffer free

            // ---- issue K(kbn)+V(kbn) into the other buffer (overlaps full compute) ----
            if (kbn >= 0) {
                const int nb = cur ^ 1;
                const unsigned* gK = g_Kp16 + hK + (size_t)kbn * 64 * 64;
                const unsigned* gV = g_V16 + ((size_t)(h * 32 + kbn) * 128) * 32;
                const uint32_t dK = sbBase + nb * KBUF * 4;
                const uint32_t dV = sbBase + (2 * KBUF + nb * VBUF) * 4;
                #pragma unroll
                for (int it = 0; it < 8; ++it) {
                    const int c = t + it * 128;
                    const int r = c >> 4, w4 = c & 15;
                    cp16(dK + (r * 64 + (w4 ^ ((r & 1) << 2)) * 4) * 4, gK + r * 64 + w4 * 4);
                }
                #pragma unroll
                for (int it = 0; it < 8; ++it) {
                    const int c = t + it * 128;
                    const int r = c >> 3, w4 = c & 7;
                    cp16(dV + (r * 32 + (w4 ^ (r & 1)) * 4) * 4, gV + r * 32 + w4 * 4);
                }
                CP_COMMIT();
            }

            const bool diag = (kb == qb);
            const int ntLim = diag ? (2 * w + 2) : 8;   // even; aligned to PV pair groups

            // ---- fused QK + softmax per nt: mma, mask, 2^s, pack to fp16 A-frags ----
            const unsigned* Ku = sm + cur * KBUF;
            unsigned pk[8][2];
            #pragma unroll
            for (int nt = 0; nt < 8; ++nt) {
                if (nt < ntLim) {
                    float sf[4] = {0.0f, 0.0f, 0.0f, 0.0f};
                    #pragma unroll
                    for (int p = 0; p < 4; ++p) {
                        const uint4 B = *(const uint4*)&Ku[(nt * 8 + lr) * 64 + ((p * 4 + lc) ^ kx) * 4];
                        mma_f16(sf, qa[2*p][0],   qa[2*p][1],   qa[2*p][2],   qa[2*p][3],   B.x, B.y);
                        mma_f16(sf, qa[2*p+1][0], qa[2*p+1][1], qa[2*p+1][2], qa[2*p+1][3], B.z, B.w);
                    }
                    float p0, p1, p2, p3;
                    if (diag) {
                        const int c0 = kb * 64 + nt * 8 + lc * 2;
                        p0 = (c0     <= s0) ? fexp2(sf[0]) : 0.0f;
                        p1 = (c0 + 1 <= s0) ? fexp2(sf[1]) : 0.0f;
                        p2 = (c0     <= s1) ? fexp2(sf[2]) : 0.0f;
                        p3 = (c0 + 1 <= s1) ? fexp2(sf[3]) : 0.0f;
                    } else {
                        p0 = fexp2(sf[0]);
                        p1 = fexp2(sf[1]);
                        p2 = fexp2(sf[2]);
                        p3 = fexp2(sf[3]);
                    }
                    ls0 += p0 + p1;
                    ls1 += p2 + p3;
                    pk[nt][0] = pack_f16x2(p0, p1);
                    pk[nt][1] = pack_f16x2(p2, p3);
                } else {
                    pk[nt][0] = 0u;
                    pk[nt][1] = 0u;
                }
            }

            // ---- O += P V : fp16; A-fragments direct from pk ----
            const unsigned* Vp = sm + 2 * KBUF + cur * VBUF;
            #pragma unroll
            for (int g = 0; g < 2; ++g) {
                const bool doA = (4 * g)     < ntLim;
                const bool doB = (4 * g + 2) < ntLim;
                if (doA || doB) {
                    #pragma unroll
                    for (int nt = 0; nt < 16; ++nt) {
                        const uint4 f4 = *(const uint4*)&Vp[(nt * 8 + lr) * 32 + ((2 * lc + g) ^ vx) * 4];
                        if (doA) mma_f16(oacc[nt], pk[4*g+0][0], pk[4*g+0][1], pk[4*g+1][0], pk[4*g+1][1], f4.x, f4.y);
                        if (doB) mma_f16(oacc[nt], pk[4*g+2][0], pk[4*g+2][1], pk[4*g+3][0], pk[4*g+3][1], f4.z, f4.w);
                    }
                }
            }

            kb = kbn;
            cur ^= 1;
        }

        // ---- epilogue ----
        ls0 += __shfl_xor_sync(0xffffffffu, ls0, 1);
        ls0 += __shfl_xor_sync(0xffffffffu, ls0, 2);
        ls1 += __shfl_xor_sync(0xffffffffu, ls1, 1);
        ls1 += __shfl_xor_sync(0xffffffffu, ls1, 2);
        const float linv0 = 1.0f / ls0;
        const float linv1 = 1.0f / ls1;
        float* O0 = O + ((size_t)s0 * HEADS + h) * DIM;
        float* O1 = O + ((size_t)s1 * HEADS + h) * DIM;
        #pragma unroll
        for (int nt = 0; nt < 16; ++nt) {
            const int col = nt * 8 + lc * 2;
            *(float2*)(O0 + col) = make_float2(oacc[nt][0] * linv0, oacc[nt][1] * linv0);
            *(float2*)(O1 + col) = make_float2(oacc[nt][2] * linv1, oacc[nt][3] * linv1);
        }

        __syncthreads();     // smem free + jobSh (next id) published
        j = jobSh;
    }
}

extern "C" void kernel_launch(void* const* d_in, const int* in_sizes, int n_in,
                              void* d_out, int out_size) {
    const float* Q = (const float*)d_in[0];
    const float* K = (const float*)d_in[1];
    const float* V = (const float*)d_in[2];
    float* O = (float*)d_out;

    const size_t smem = SMEM_WORDS * sizeof(unsigned);   // 65536 B
    static bool attr_set = false;
    if (!attr_set) {
        cudaFuncSetAttribute(sparse_attn_fu_kernel,
                             cudaFuncAttributeMaxDynamicSharedMemorySize, (int)smem);
        attr_set = true;
    }

    prepack_all_kernel<<<6144, 256>>>(K, V);          // also resets g_jobCtr
    sparse_attn_fu_kernel<<<GRID_PERSIST, 128, smem>>>(Q, O);
}

// round 16
// speedup vs baseline: 1.0149x; 1.0149x over previous
#include <cuda_runtime.h>
#include <cstdint>

#define HEADS 32
#define S_LEN 2048
#define DIM   128
#define LOCAL 16

#define KBUF (64*64)            // 4096 words (K row = 64 words, XOR-swizzled)
#define VBUF (128*32)           // 4096 words (V dim-row = 32 words, XOR-swizzled)
#define SMEM_WORDS (2*KBUF + 2*VBUF)   // 16384 words = 65536 B
#define NJOBS 1024
#define GRID_PERSIST 444

__device__ unsigned g_Kp16[(size_t)HEADS * S_LEN * 64];
__device__ unsigned g_V16 [(size_t)HEADS * 32 * 128 * 32];
__device__ unsigned g_jobCtr;

__device__ __forceinline__ unsigned pack_f16x2(float lo_el, float hi_el) {
    unsigned r; asm("cvt.rn.f16x2.f32 %0, %1, %2;" : "=r"(r) : "f"(hi_el), "f"(lo_el)); return r;
}
__device__ __forceinline__ float fexp2(float x) {
    float y; asm("ex2.approx.ftz.f32 %0, %1;" : "=f"(y) : "f"(x)); return y;
}
__device__ __forceinline__ void mma_f16(float c[4],
                                        unsigned a0, unsigned a1, unsigned a2, unsigned a3,
                                        unsigned b0, unsigned b1) {
    asm volatile(
        "mma.sync.aligned.m16n8k16.row.col.f32.f16.f16.f32 "
        "{%0,%1,%2,%3}, {%4,%5,%6,%7}, {%8,%9}, {%0,%1,%2,%3};"
        : "+f"(c[0]), "+f"(c[1]), "+f"(c[2]), "+f"(c[3])
        : "r"(a0), "r"(a1), "r"(a2), "r"(a3), "r"(b0), "r"(b1));
}
__device__ __forceinline__ uint32_t smem_u32(const void* p) {
    uint32_t a;
    asm("{ .reg .u64 t; cvta.to.shared.u64 t, %1; cvt.u32.u64 %0, t; }" : "=r"(a) : "l"(p));
    return a;
}
__device__ __forceinline__ void cp16(uint32_t dst, const void* src) {
    asm volatile("cp.async.ca.shared.global [%0], [%1], 16;" :: "r"(dst), "l"(src));
}
#define CP_COMMIT() asm volatile("cp.async.commit_group;" ::: "memory")
#define CP_WAIT0()  asm volatile("cp.async.wait_group 0;" ::: "memory")

// ---- merged prepass: K fp16x2 mma-ready + V fp16x2 dim-major permuted + counter reset ----
__global__ __launch_bounds__(256)
void prepack_all_kernel(const float* __restrict__ K, const float* __restrict__ V) {
    if (blockIdx.x == 0 && threadIdx.x == 0) g_jobCtr = 0u;
    if (blockIdx.x < 4096) {
        const int gid = blockIdx.x * 256 + threadIdx.x;
        const int rid = gid >> 4;
        const int j   = gid & 15;
        const int h   = rid >> 11;
        const int s   = rid & 2047;
        const size_t src_row = ((size_t)s * HEADS + h) * DIM;
        unsigned kw[4];
        #pragma unroll
        for (int m = 0; m < 4; ++m) {
            const int i  = 4 * j + m;
            const int p  = i >> 4;
            const int lc = (i >> 2) & 3;
            const int s2 = i & 3;
            const int kg = 2 * p + (s2 >> 1);
            const int d  = kg * 16 + lc * 4 + (s2 & 1) * 2;
            const float2 v = __ldg((const float2*)(K + src_row + d));
            kw[m] = pack_f16x2(v.x, v.y);
        }
        *(uint4*)&g_Kp16[(size_t)rid * 64 + j * 4] = make_uint4(kw[0], kw[1], kw[2], kw[3]);
    } else {
        const int gid = (blockIdx.x - 4096) * 256 + threadIdx.x;
        const int rid = gid >> 10;       // h*32 + kb
        const int t2  = gid & 1023;
        const int d   = t2 & 127;
        const int j   = t2 >> 7;
        const int h   = rid >> 5;
        const int kb  = rid & 31;
        unsigned vw[4];
        #pragma unroll
        for (int m = 0; m < 4; ++m) {
            const int wp = 4 * j + m;
            const int w  = (wp >> 3) + (wp & 7) * 4;
            const int tok = kb * 64 + 2 * w;
            const float a = __ldg(V + ((size_t)tok       * HEADS + h) * DIM + d);
            const float b = __ldg(V + ((size_t)(tok + 1) * HEADS + h) * DIM + d);
            vw[m] = pack_f16x2(a, b);
        }
        *(uint4*)&g_V16[((size_t)rid * 128 + d) * 32 + 4 * j] = make_uint4(vw[0], vw[1], vw[2], vw[3]);
    }
}

__global__ __launch_bounds__(128, 3)
void sparse_attn_sw2_kernel(const float* __restrict__ Q,
                            float* __restrict__ O) {
    extern __shared__ unsigned sm[];
    __shared__ unsigned jobSh;
    const uint32_t sbBase = smem_u32(sm);

    const int t    = threadIdx.x;   // 0..127
    const int w    = t >> 5;
    const int lane = t & 31;
    const int lr   = lane >> 2;
    const int lc   = lane & 3;
    const int kx   = (lr & 1) << 2;   // K swizzle term
    const int vx   = lr & 1;          // V swizzle term
    const float scale2 = 0.12751743f; // log2(e)/sqrt(128)

    // prefetch pattern: jobSh holds the NEXT job id, published at each job-end barrier
    if (t == 0) jobSh = atomicAdd(&g_jobCtr, 1u);
    __syncthreads();
    unsigned j = jobSh;

    for (;;) {
        if (j >= NJOBS) break;
        if (t == 0) jobSh = atomicAdd(&g_jobCtr, 1u);   // fetch next job id early

        const int qb = 31 - (int)(j >> 5);    // heavy-first (LPT)
        const int h  = (int)(j & 31u);

        const int s0 = qb * 64 + w * 16 + lr;
        const int s1 = s0 + 8;
        const size_t hK = (size_t)h * S_LEN * 64;

        // ---- Q fragments (scale*log2e folded) ----
        unsigned qa[8][4];
        {
            const float* Qp0 = Q + ((size_t)s0 * HEADS + h) * DIM;
            const float* Qp1 = Q + ((size_t)s1 * HEADS + h) * DIM;
            #pragma unroll
            for (int kg = 0; kg < 8; ++kg) {
                const float4 A = *(const float4*)(Qp0 + kg * 16 + lc * 4);
                const float4 B = *(const float4*)(Qp1 + kg * 16 + lc * 4);
                qa[kg][0] = pack_f16x2(A.x * scale2, A.y * scale2);
                qa[kg][1] = pack_f16x2(B.x * scale2, B.y * scale2);
                qa[kg][2] = pack_f16x2(A.z * scale2, A.w * scale2);
                qa[kg][3] = pack_f16x2(B.z * scale2, B.w * scale2);
            }
        }

        float oacc[16][4];
        #pragma unroll
        for (int nt = 0; nt < 16; ++nt)
            #pragma unroll
            for (int q4 = 0; q4 < 4; ++q4) oacc[nt][q4] = 0.0f;
        float ls0 = 0.0f, ls1 = 0.0f;

        // ---- first allowed kv block; prologue K+V into buffer 0 ----
        int kb = 0;
        while (!(((qb - kb) < LOCAL) || (((kb + h + 1) & 7) == 0))) ++kb;
        {
            const unsigned* gK = g_Kp16 + hK + (size_t)kb * 64 * 64;
            const unsigned* gV = g_V16 + ((size_t)(h * 32 + kb) * 128) * 32;
            #pragma unroll
            for (int it = 0; it < 8; ++it) {
                const int c = t + it * 128;
                const int r = c >> 4, w4 = c & 15;
                cp16(sbBase + (r * 64 + (w4 ^ ((r & 1) << 2)) * 4) * 4, gK + r * 64 + w4 * 4);
            }
            #pragma unroll
            for (int it = 0; it < 8; ++it) {
                const int c = t + it * 128;
                const int r = c >> 3, w4 = c & 7;
                cp16(sbBase + (2 * KBUF + r * 32 + (w4 ^ (r & 1)) * 4) * 4, gV + r * 32 + w4 * 4);
            }
            CP_COMMIT();
        }

        int cur = 0;
        while (kb >= 0) {
            int kbn = kb + 1;
            while (kbn <= qb && !(((qb - kbn) < LOCAL) || (((kbn + h + 1) & 7) == 0))) ++kbn;
            if (kbn > qb) kbn = -1;

            CP_WAIT0();          // K(kb)+V(kb) resident (issued a full phase ago)
            __syncthreads();     // visible to all; other buffer free

            // ---- issue K(kbn)+V(kbn) into the other buffer (overlaps full compute) ----
            if (kbn >= 0) {
                const int nb = cur ^ 1;
                const unsigned* gK = g_Kp16 + hK + (size_t)kbn * 64 * 64;
                const unsigned* gV = g_V16 + ((size_t)(h * 32 + kbn) * 128) * 32;
                const uint32_t dK = sbBase + nb * KBUF * 4;
                const uint32_t dV = sbBase + (2 * KBUF + nb * VBUF) * 4;
                #pragma unroll
                for (int it = 0; it < 8; ++it) {
                    const int c = t + it * 128;
                    const int r = c >> 4, w4 = c & 15;
                    cp16(dK + (r * 64 + (w4 ^ ((r & 1) << 2)) * 4) * 4, gK + r * 64 + w4 * 4);
                }
                #pragma unroll
                for (int it = 0; it < 8; ++it) {
                    const int c = t + it * 128;
                    const int r = c >> 3, w4 = c & 7;
                    cp16(dV + (r * 32 + (w4 ^ (r & 1)) * 4) * 4, gV + r * 32 + w4 * 4);
                }
                CP_COMMIT();
            }

            const bool diag = (kb == qb);
            const int ntLim = diag ? (2 * w + 2) : 8;

            // ---- S = Q K^T : fp16 m16n8k16 burst (max ILP across nt tiles) ----
            const unsigned* Ku = sm + cur * KBUF;
            float sf[8][4];
            #pragma unroll
            for (int nt = 0; nt < 8; ++nt)
                #pragma unroll
                for (int q4 = 0; q4 < 4; ++q4) sf[nt][q4] = 0.0f;

            #pragma unroll
            for (int p = 0; p < 4; ++p) {
                #pragma unroll
                for (int nt = 0; nt < 8; ++nt) {
                    if (nt < ntLim) {
                        const uint4 B = *(const uint4*)&Ku[(nt * 8 + lr) * 64 + ((p * 4 + lc) ^ kx) * 4];
                        mma_f16(sf[nt], qa[2*p][0],   qa[2*p][1],   qa[2*p][2],   qa[2*p][3],   B.x, B.y);
                        mma_f16(sf[nt], qa[2*p+1][0], qa[2*p+1][1], qa[2*p+1][2], qa[2*p+1][3], B.z, B.w);
                    }
                }
            }

            // ---- softmax burst: p = 2^s; fixed-max (shift-invariant) ----
            if (diag) {
                #pragma unroll
                for (int nt = 0; nt < 8; ++nt) {
                    if (nt < ntLim) {
                        const int c0 = kb * 64 + nt * 8 + lc * 2;
                        sf[nt][0] = (c0     <= s0) ? fexp2(sf[nt][0]) : 0.0f;
                        sf[nt][1] = (c0 + 1 <= s0) ? fexp2(sf[nt][1]) : 0.0f;
                        sf[nt][2] = (c0     <= s1) ? fexp2(sf[nt][2]) : 0.0f;
                        sf[nt][3] = (c0 + 1 <= s1) ? fexp2(sf[nt][3]) : 0.0f;
                        ls0 += sf[nt][0] + sf[nt][1];
                        ls1 += sf[nt][2] + sf[nt][3];
                    }
                }
            } else {
                #pragma unroll
                for (int nt = 0; nt < 8; ++nt) {
                    sf[nt][0] = fexp2(sf[nt][0]);
                    sf[nt][1] = fexp2(sf[nt][1]);
                    sf[nt][2] = fexp2(sf[nt][2]);
                    sf[nt][3] = fexp2(sf[nt][3]);
                    ls0 += sf[nt][0] + sf[nt][1];
                    ls1 += sf[nt][2] + sf[nt][3];
                }
            }

            // ---- O += P V : fp16; P from C fragments directly ----
            const unsigned* Vp = sm + 2 * KBUF + cur * VBUF;
            #pragma unroll
            for (int g = 0; g < 2; ++g) {
                const bool doA = (4 * g)     < ntLim;
                const bool doB = (4 * g + 2) < ntLim;
                if (doA || doB) {
                    unsigned aA0, aA1, aA2, aA3, aB0, aB1, aB2, aB3;
                    if (doA) {
                        aA0 = pack_f16x2(sf[4*g+0][0], sf[4*g+0][1]);
                        aA1 = pack_f16x2(sf[4*g+0][2], sf[4*g+0][3]);
                        aA2 = pack_f16x2(sf[4*g+1][0], sf[4*g+1][1]);
                        aA3 = pack_f16x2(sf[4*g+1][2], sf[4*g+1][3]);
                    }
                    if (doB) {
                        aB0 = pack_f16x2(sf[4*g+2][0], sf[4*g+2][1]);
                        aB1 = pack_f16x2(sf[4*g+2][2], sf[4*g+2][3]);
                        aB2 = pack_f16x2(sf[4*g+3][0], sf[4*g+3][1]);
                        aB3 = pack_f16x2(sf[4*g+3][2], sf[4*g+3][3]);
                    }
                    #pragma unroll
                    for (int nt = 0; nt < 16; ++nt) {
                        const uint4 f4 = *(const uint4*)&Vp[(nt * 8 + lr) * 32 + ((2 * lc + g) ^ vx) * 4];
                        if (doA) mma_f16(oacc[nt], aA0, aA1, aA2, aA3, f4.x, f4.y);
                        if (doB) mma_f16(oacc[nt], aB0, aB1, aB2, aB3, f4.z, f4.w);
                    }
                }
            }

            kb = kbn;
            cur ^= 1;
        }

        // ---- epilogue ----
        ls0 += __shfl_xor_sync(0xffffffffu, ls0, 1);
        ls0 += __shfl_xor_sync(0xffffffffu, ls0, 2);
        ls1 += __shfl_xor_sync(0xffffffffu, ls1, 1);
        ls1 += __shfl_xor_sync(0xffffffffu, ls1, 2);
        const float linv0 = 1.0f / ls0;
        const float linv1 = 1.0f / ls1;
        float* O0 = O + ((size_t)s0 * HEADS + h) * DIM;
        float* O1 = O + ((size_t)s1 * HEADS + h) * DIM;
        #pragma unroll
        for (int nt = 0; nt < 16; ++nt) {
            const int col = nt * 8 + lc * 2;
            *(float2*)(O0 + col) = make_float2(oacc[nt][0] * linv0, oacc[nt][1] * linv0);
            *(float2*)(O1 + col) = make_float2(oacc[nt][2] * linv1, oacc[nt][3] * linv1);
        }

        __syncthreads();     // smem free for next job + jobSh (next id) published
        j = jobSh;
    }
}

extern "C" void kernel_launch(void* const* d_in, const int* in_sizes, int n_in,
                              void* d_out, int out_size) {
    const float* Q = (const float*)d_in[0];
    const float* K = (const float*)d_in[1];
    const float* V = (const float*)d_in[2];
    float* O = (float*)d_out;

    const size_t smem = SMEM_WORDS * sizeof(unsigned);   // 65536 B
    static bool attr_set = false;
    if (!attr_set) {
        cudaFuncSetAttribute(sparse_attn_sw2_kernel,
                             cudaFuncAttributeMaxDynamicSharedMemorySize, (int)smem);
        attr_set = true;
    }

    prepack_all_kernel<<<8192, 256>>>(K, V);          // also resets g_jobCtr
    sparse_attn_sw2_kernel<<<GRID_PERSIST, 128, smem>>>(Q, O);
}